// round 1
// baseline (speedup 1.0000x reference)
#include <cuda_runtime.h>

// AdderNet 2D (K=3, S=1, P=1): out[n,f,y,x] = -sum_{c,i,j} |W[f,c,i,j] - xpad[n,c,y+i,x+j]|
// x: [8,64,32,32] f32, W: [64,64,3,3] f32, out: [8,64,32,32] f32.

#define CIN   64
#define NFILT 64
#define HW    32
#define NIMG  8

#define FG    16              // filters per CTA
#define RT    8               // output rows per CTA
#define XROWS (RT + 2)        // padded rows in slab
#define XCOLS 34              // padded cols

#define SX_ELEMS (CIN * XROWS * XCOLS)   // 21760 floats = 87040 B
#define SW_ELEMS (CIN * 9 * FG)          // 9216 floats  = 36864 B
#define SMEM_BYTES ((SX_ELEMS + SW_ELEMS) * 4)

__global__ __launch_bounds__(256, 1)
void adder2d_kernel(const float* __restrict__ x,
                    const float* __restrict__ W,
                    float* __restrict__ out)
{
    extern __shared__ float smem[];
    float* sX = smem;                 // [c][r][col] : padded input slab, zeros on border
    float* sW = smem + SX_ELEMS;      // [k=c*9+i*3+j][ff] : NEGATED weights, filters contiguous

    const int tid = threadIdx.x;
    const int fg  = blockIdx.x;       // 0..3  filter group
    const int rt  = blockIdx.y;       // 0..3  row tile
    const int n   = blockIdx.z;       // 0..7  image
    const int y0  = rt * RT;
    const int f0  = fg * FG;

    // ---- load padded x slab for this (n, row tile), all 64 channels ----
    const float* xn = x + (size_t)n * (CIN * HW * HW);
    for (int idx = tid; idx < SX_ELEMS; idx += 256) {
        int c   = idx / (XROWS * XCOLS);
        int rem = idx - c * (XROWS * XCOLS);
        int r   = rem / XCOLS;
        int col = rem - r * XCOLS;
        int gr  = y0 - 1 + r;         // global row
        int gc  = col - 1;            // global col
        float v = 0.0f;
        if ((unsigned)gr < HW && (unsigned)gc < HW)
            v = xn[(c * HW + gr) * HW + gc];
        sX[idx] = v;
    }

    // ---- load NEGATED weight tile: sW[k*FG + ff] = -W[(f0+ff)*576 + k] ----
    for (int idx = tid; idx < SW_ELEMS; idx += 256) {
        int ff = idx / (CIN * 9);
        int k  = idx - ff * (CIN * 9);
        sW[k * FG + ff] = -W[(f0 + ff) * (CIN * 9) + k];
    }
    __syncthreads();

    // ---- each thread: one (y,col) position, 16 filters as 8 packed f32x2 accumulators ----
    const int y   = tid >> 5;         // 0..7
    const int col = tid & 31;         // 0..31

    unsigned long long acc[FG / 2];
#pragma unroll
    for (int p = 0; p < FG / 2; p++) acc[p] = 0ULL;   // (+0.0f, +0.0f)

#pragma unroll 1
    for (int c = 0; c < CIN; c++) {
        const float* sxc = sX + c * (XROWS * XCOLS) + y * XCOLS + col;
        const float* swc = sW + c * 9 * FG;
#pragma unroll
        for (int i = 0; i < 3; i++) {
#pragma unroll
            for (int j = 0; j < 3; j++) {
                float xv = sxc[i * XCOLS + j];                 // coalesced LDS.32
                unsigned xr = __float_as_uint(xv);
                unsigned long long xx;
                asm("mov.b64 %0, {%1, %1};" : "=l"(xx) : "r"(xr));
                const unsigned long long* wrow =
                    (const unsigned long long*)(swc + (i * 3 + j) * FG);
#pragma unroll
                for (int p = 0; p < FG / 2; p++) {
                    unsigned long long w2 = wrow[p];           // broadcast LDS.64 (-W pair)
                    unsigned long long d;
                    asm("add.rn.f32x2 %0, %1, %2;" : "=l"(d) : "l"(xx), "l"(w2)); // x - W
                    d &= 0x7FFFFFFF7FFFFFFFULL;                // |.| on both lanes (2x LOP3, ALU pipe)
                    asm("add.rn.f32x2 %0, %0, %1;" : "+l"(acc[p]) : "l"(d));
                }
            }
        }
    }

    // ---- epilogue: out = -acc ----
    float* outp = out + (((size_t)n * NFILT + f0) * HW + (y0 + y)) * HW + col;
#pragma unroll
    for (int p = 0; p < FG / 2; p++) {
        float lo = __uint_as_float((unsigned)(acc[p] & 0xFFFFFFFFULL));
        float hi = __uint_as_float((unsigned)(acc[p] >> 32));
        outp[(2 * p)     * (HW * HW)] = -lo;
        outp[(2 * p + 1) * (HW * HW)] = -hi;
    }
}

extern "C" void kernel_launch(void* const* d_in, const int* in_sizes, int n_in,
                              void* d_out, int out_size)
{
    const float* x = (const float*)d_in[0];
    const float* W = (const float*)d_in[1];
    // Defensive: metadata order should be (x, W); swap if sizes indicate otherwise.
    if (n_in >= 2 && in_sizes[0] == NFILT * CIN * 9 && in_sizes[1] == NIMG * CIN * HW * HW) {
        const float* t = x; x = W; W = t;
    }
    float* out = (float*)d_out;

    static int smem_set = -1;
    if (smem_set < 0) {
        cudaFuncSetAttribute(adder2d_kernel,
                             cudaFuncAttributeMaxDynamicSharedMemorySize, SMEM_BYTES);
        smem_set = 1;
    }

    dim3 grid(NFILT / FG, HW / RT, NIMG);   // 4 x 4 x 8 = 128 CTAs
    adder2d_kernel<<<grid, 256, SMEM_BYTES>>>(x, W, out);
}